// round 7
// baseline (speedup 1.0000x reference)
#include <cuda_runtime.h>
#include <cuda_fp16.h>
#include <cstdint>

using f16 = __half;

constexpr int HIDDEN = 1024;
constexpr int INTER  = 1408;
constexpr int NEXP   = 8;
constexpr int TOKENS = 8192;

// ---------------- scratch (device globals; no allocation allowed) ----------
__device__ __align__(256) f16 g_x[(size_t)TOKENS * HIDDEN];
__device__ __align__(256) f16 g_w1[(size_t)NEXP * HIDDEN * 2 * INTER];  // [E][K][N] native
__device__ __align__(256) f16 g_w2[(size_t)NEXP * INTER * HIDDEN];      // [E][K][N] native
__device__ __align__(256) f16 g_h[(size_t)TOKENS * INTER];

// ---------------- helpers ---------------------------------------------------
__device__ __forceinline__ void load_offsets(const void* tpe_ptr, int e,
                                             int& off, int& cnt) {
    const int* p32 = (const int*)tpe_ptr;
    int s = 0;
#pragma unroll
    for (int i = 0; i < NEXP; i++) s += p32[i];
    off = 0; cnt = 0;
    if (s == TOKENS) {
#pragma unroll
        for (int i = 0; i < NEXP; i++) {
            int v = p32[i];
            if (i < e)  off += v;
            if (i == e) cnt = v;
        }
    } else {
        const long long* p64 = (const long long*)tpe_ptr;
#pragma unroll
        for (int i = 0; i < NEXP; i++) {
            int v = (int)p64[i];
            if (i < e)  off += v;
            if (i == e) cnt = v;
        }
    }
}

__device__ __forceinline__ uint32_t smem_u32(const void* p) {
    uint32_t a;
    asm("{ .reg .u64 t; cvta.to.shared.u64 t, %1; cvt.u32.u64 %0, t; }"
        : "=r"(a) : "l"(p));
    return a;
}

#define SW128(o) ((o) ^ (((o) >> 3) & 0x70))

__device__ __forceinline__ void cp16(uint32_t s, const void* g, int nbytes) {
    asm volatile("cp.async.cg.shared.global [%0], [%1], 16, %2;"
                 :: "r"(s), "l"(g), "r"(nbytes) : "memory");
}

__device__ __forceinline__ void ldmx4(uint32_t* r, uint32_t addr) {
    asm volatile("ldmatrix.sync.aligned.m8n8.x4.shared.b16 {%0,%1,%2,%3}, [%4];"
                 : "=r"(r[0]), "=r"(r[1]), "=r"(r[2]), "=r"(r[3]) : "r"(addr));
}

__device__ __forceinline__ void ldmx4t(uint32_t* r, uint32_t addr) {
    asm volatile("ldmatrix.sync.aligned.m8n8.x4.trans.shared.b16 {%0,%1,%2,%3}, [%4];"
                 : "=r"(r[0]), "=r"(r[1]), "=r"(r[2]), "=r"(r[3]) : "r"(addr));
}

__device__ __forceinline__ void mma16816(float* c, const uint32_t* a, const uint32_t* b) {
    asm volatile("mma.sync.aligned.m16n8k16.row.col.f32.f16.f16.f32 "
                 "{%0,%1,%2,%3}, {%4,%5,%6,%7}, {%8,%9}, {%0,%1,%2,%3};"
                 : "+f"(c[0]), "+f"(c[1]), "+f"(c[2]), "+f"(c[3])
                 : "r"(a[0]), "r"(a[1]), "r"(a[2]), "r"(a[3]),
                   "r"(b[0]), "r"(b[1]));
}

// ---------------- conversion kernel (streaming f32 -> f16) ------------------
__global__ __launch_bounds__(256) void convert_f16(
    const float* __restrict__ src, f16* __restrict__ dst, int n4)
{
    int i = blockIdx.x * 256 + threadIdx.x;
    if (i >= n4) return;
    float4 v = ((const float4*)src)[i];
    __half2 a = __floats2half2_rn(v.x, v.y);
    __half2 b = __floats2half2_rn(v.z, v.w);
    ((uint2*)dst)[i] = make_uint2(*(uint32_t*)&a, *(uint32_t*)&b);
}

// ---------------- HMMA grouped GEMM ------------------------------------------
// CTA 128m x 128n, BK=64, 256 threads (8 warps, 2m x 4n, warp 64x32).
// A smem: [m][k] 128B rows, SW128.  B smem: [k][n] 256B rows, chunk^k swizzle.
constexpr int BM = 128, BK = 64;
constexpr int A_SZ = BM * BK * 2;                // 16384
constexpr int B_SZ = BK * 128 * 2;               // 16384
constexpr int STAGE_SZ = A_SZ + B_SZ;            // 32768
constexpr int NSTAGE = 3;
constexpr int SMEM_BYTES = NSTAGE * STAGE_SZ;    // 98304 -> 2 CTAs/SM

template <int K, bool FUSED>
__global__ __launch_bounds__(256, 2) void moe_gemm_hmma(
    const f16* __restrict__ A, const f16* __restrict__ B,
    float* __restrict__ Cout, f16* __restrict__ H,
    const void* __restrict__ tpe)
{
    const int e = blockIdx.z;
    int off, cnt;
    load_offsets(tpe, e, off, cnt);
    const int m0 = blockIdx.y * BM;
    if (m0 >= cnt) return;
    const int n0 = blockIdx.x * (FUSED ? 64 : 128);
    constexpr int NFULL = FUSED ? 2 * INTER : HIDDEN;

    extern __shared__ char smem[];
    const uint32_t sbase = smem_u32(smem);
    const int tid = threadIdx.x, wid = tid >> 5, lane = tid & 31;

    const f16* Ag = A + (size_t)off * K;
    const f16* Bg = B + (size_t)e * ((size_t)K * NFULL);

    // Warp tile: 64m x 32n; warps 2(m) x 4(n)
    const int wm = (wid & 1) * 64;
    const int wn = (wid >> 1) * 32;
    const int g = lane >> 3, r8 = lane & 7;

    int a_base[4];
#pragma unroll
    for (int mi = 0; mi < 4; mi++)
        a_base[mi] = (wm + mi * 16 + r8 + (g & 1) * 8) * 128 + (g >> 1) * 16;

    const int b_k_byte = ((g & 1) * 8 + r8) * 256;
    const int b_chunk_half = (g >> 1);

    // cooperative load indices
    const int a_row0 = tid >> 3, a_ks = tid & 7;   // A: 1024 16B units / 4 iters
    const int b_k0 = tid >> 4, b_c = tid & 15;     // B: 1024 16B units / 4 iters

    float acc[4][4][4];
#pragma unroll
    for (int mi = 0; mi < 4; mi++)
#pragma unroll
        for (int ni = 0; ni < 4; ni++)
#pragma unroll
            for (int q = 0; q < 4; q++) acc[mi][ni][q] = 0.0f;

    constexpr int NCH = K / BK;

    auto load_stage = [&](int c) {
        const uint32_t st = sbase + (c % NSTAGE) * STAGE_SZ;
        const int k0 = c * BK;
#pragma unroll
        for (int i = 0; i < 4; ++i) {
            int row = a_row0 + i * 32;
            int gr = m0 + row;
            int nb = (gr < cnt) ? 16 : 0;
            int grc = (gr < cnt) ? gr : 0;
            cp16(st + SW128(row * 128 + a_ks * 16),
                 Ag + (size_t)grc * K + k0 + a_ks * 8, nb);
        }
#pragma unroll
        for (int i = 0; i < 4; ++i) {
            int k = b_k0 + i * 16;
            int wc = b_c ^ (k & 7);
            int gcol = FUSED ? ((b_c < 8) ? (n0 + b_c * 8)
                                          : (INTER + n0 + (b_c - 8) * 8))
                             : (n0 + b_c * 8);
            cp16(st + A_SZ + k * 256 + wc * 16,
                 Bg + (size_t)(k0 + k) * NFULL + gcol, 16);
        }
        asm volatile("cp.async.commit_group;" ::: "memory");
    };

    // B fragment loader: one kk (k16), n32 span -> 2 ldmx4t -> 4 n8 frags
    auto ldB = [&](uint32_t sB, int kk, uint32_t (*b)[2]) {
#pragma unroll
        for (int j = 0; j < 2; ++j) {
            int chunk = (((wn >> 3) + j * 2 + b_chunk_half) ^ r8) & 15;
            uint32_t t[4];
            ldmx4t(t, sB + kk * 16 * 256 + b_k_byte + chunk * 16);
            b[j * 2][0] = t[0];     b[j * 2][1] = t[1];
            b[j * 2 + 1][0] = t[2]; b[j * 2 + 1][1] = t[3];
        }
    };

    load_stage(0);
    if (NCH > 1) load_stage(1);

    for (int c = 0; c < NCH; ++c) {
        if (c + 1 < NCH)
            asm volatile("cp.async.wait_group 1;" ::: "memory");
        else
            asm volatile("cp.async.wait_group 0;" ::: "memory");
        __syncthreads();
        // Issue next-stage loads AFTER the sync: all warps have finished
        // reading stage (c-1)%3, which these cp.async writes overwrite.
        if (c + 2 < NCH) load_stage(c + 2);

        const uint32_t st = sbase + (c % NSTAGE) * STAGE_SZ;
        const uint32_t sA = st, sB = st + A_SZ;

        uint32_t bbuf[2][4][2];
        ldB(sB, 0, bbuf[0]);
#pragma unroll
        for (int kk = 0; kk < 4; ++kk) {
            const int cur = kk & 1;
            if (kk < 3) ldB(sB, kk + 1, bbuf[cur ^ 1]);
#pragma unroll
            for (int mi = 0; mi < 4; mi++) {
                uint32_t a[4];
                ldmx4(a, sA + SW128(a_base[mi] + kk * 32));
#pragma unroll
                for (int ni = 0; ni < 4; ni++)
                    mma16816(acc[mi][ni], a, bbuf[cur][ni]);
            }
        }
        // no bottom __syncthreads: next iteration's top sync provides the
        // ordering before any overwrite of this stage is issued.
    }
    __syncthreads();

    // ---------------- epilogue: stage accum through SMEM ----------------
    float* shf = (float*)smem;   // [128][132] fp32 = 67.6 KB (< 96 KB)
    const int crow = wm + (lane >> 2);
    const int ccol0 = wn + (lane & 3) * 2;
#pragma unroll
    for (int mi = 0; mi < 4; mi++)
#pragma unroll
        for (int ni = 0; ni < 4; ni++) {
            int rr = crow + mi * 16, cc = ccol0 + ni * 8;
            *(float2*)&shf[rr * 132 + cc]       = make_float2(acc[mi][ni][0], acc[mi][ni][1]);
            *(float2*)&shf[(rr + 8) * 132 + cc] = make_float2(acc[mi][ni][2], acc[mi][ni][3]);
        }
    __syncthreads();

    if (FUSED) {
        // cols [0,64) = gate(n0+j), [64,128) = up(n0+j); h = silu(g)*u
        for (int idx = tid; idx < 128 * 32; idx += 256) {
            int rr = idx >> 5, j = (idx & 31) * 2;
            if (m0 + rr >= cnt) continue;
            float g0 = shf[rr * 132 + j],      g1 = shf[rr * 132 + j + 1];
            float u0 = shf[rr * 132 + 64 + j], u1 = shf[rr * 132 + 64 + j + 1];
            float h0 = u0 * g0 / (1.0f + __expf(-g0));
            float h1 = u1 * g1 / (1.0f + __expf(-g1));
            __half2 hp = __floats2half2_rn(h0, h1);
            *(uint32_t*)(H + (size_t)(off + m0 + rr) * INTER + n0 + j) =
                *(uint32_t*)&hp;
        }
    } else {
        for (int idx = tid; idx < 128 * 32; idx += 256) {
            int rr = idx >> 5, cu = idx & 31;
            if (m0 + rr >= cnt) continue;
            *(float4*)(Cout + (size_t)(off + m0 + rr) * HIDDEN + n0 + cu * 4) =
                *(float4*)&shf[rr * 132 + cu * 4];
        }
    }
}

// ---------------- launch -----------------------------------------------------
extern "C" void kernel_launch(void* const* d_in, const int* in_sizes, int n_in,
                              void* d_out, int out_size) {
    const float* x    = (const float*)d_in[0];
    const float* w1   = (const float*)d_in[1];
    const float* w2   = (const float*)d_in[2];
    const void*  tpe  = d_in[3];
    float* out = (float*)d_out;

    f16 *xf, *w1f, *w2f, *hf;
    cudaGetSymbolAddress((void**)&xf,  g_x);
    cudaGetSymbolAddress((void**)&w1f, g_w1);
    cudaGetSymbolAddress((void**)&w2f, g_w2);
    cudaGetSymbolAddress((void**)&hf,  g_h);

    int nx = TOKENS * HIDDEN / 4;
    int n1 = NEXP * HIDDEN * 2 * INTER / 4;
    int n2 = NEXP * INTER * HIDDEN / 4;
    convert_f16<<<(nx + 255) / 256, 256>>>(x, xf, nx);
    convert_f16<<<(n1 + 255) / 256, 256>>>(w1, w1f, n1);
    convert_f16<<<(n2 + 255) / 256, 256>>>(w2, w2f, n2);

    cudaFuncSetAttribute(moe_gemm_hmma<HIDDEN, true>,
                         cudaFuncAttributeMaxDynamicSharedMemorySize, SMEM_BYTES);
    cudaFuncSetAttribute(moe_gemm_hmma<INTER, false>,
                         cudaFuncAttributeMaxDynamicSharedMemorySize, SMEM_BYTES);

    // GEMM1 (fused swiglu): each n-tile covers 64 gate + 64 up columns
    moe_gemm_hmma<HIDDEN, true><<<dim3(INTER / 64, TOKENS / 128, NEXP), 256, SMEM_BYTES>>>(
        xf, w1f, nullptr, hf, tpe);
    // GEMM2
    moe_gemm_hmma<INTER, false><<<dim3(HIDDEN / 128, TOKENS / 128, NEXP), 256, SMEM_BYTES>>>(
        hf, w2f, out, nullptr, tpe);
}

// round 8
// speedup vs baseline: 1.4665x; 1.4665x over previous
#include <cuda_runtime.h>
#include <cuda_fp16.h>
#include <cstdint>

using f16 = __half;

constexpr int HIDDEN = 1024;
constexpr int INTER  = 1408;
constexpr int NEXP   = 8;
constexpr int TOKENS = 8192;

// ---------------- scratch (device globals; no allocation allowed) ----------
__device__ __align__(256) f16 g_x[(size_t)TOKENS * HIDDEN];
__device__ __align__(256) f16 g_w1[(size_t)NEXP * HIDDEN * 2 * INTER];  // [E][K][N] native
__device__ __align__(256) f16 g_w2[(size_t)NEXP * INTER * HIDDEN];      // [E][K][N] native
__device__ __align__(256) f16 g_h[(size_t)TOKENS * INTER];

// ---------------- helpers ---------------------------------------------------
__device__ __forceinline__ void load_offsets(const void* tpe_ptr, int e,
                                             int& off, int& cnt) {
    const int* p32 = (const int*)tpe_ptr;
    int s = 0;
#pragma unroll
    for (int i = 0; i < NEXP; i++) s += p32[i];
    off = 0; cnt = 0;
    if (s == TOKENS) {
#pragma unroll
        for (int i = 0; i < NEXP; i++) {
            int v = p32[i];
            if (i < e)  off += v;
            if (i == e) cnt = v;
        }
    } else {
        const long long* p64 = (const long long*)tpe_ptr;
#pragma unroll
        for (int i = 0; i < NEXP; i++) {
            int v = (int)p64[i];
            if (i < e)  off += v;
            if (i == e) cnt = v;
        }
    }
}

__device__ __forceinline__ uint32_t smem_u32(const void* p) {
    uint32_t a;
    asm("{ .reg .u64 t; cvta.to.shared.u64 t, %1; cvt.u32.u64 %0, t; }"
        : "=r"(a) : "l"(p));
    return a;
}

#define SW128(o) ((o) ^ (((o) >> 3) & 0x70))

__device__ __forceinline__ void cp16(uint32_t s, const void* g, int nbytes) {
    asm volatile("cp.async.cg.shared.global [%0], [%1], 16, %2;"
                 :: "r"(s), "l"(g), "r"(nbytes) : "memory");
}

__device__ __forceinline__ void ldmx4(uint32_t* r, uint32_t addr) {
    asm volatile("ldmatrix.sync.aligned.m8n8.x4.shared.b16 {%0,%1,%2,%3}, [%4];"
                 : "=r"(r[0]), "=r"(r[1]), "=r"(r[2]), "=r"(r[3]) : "r"(addr));
}

__device__ __forceinline__ void ldmx4t(uint32_t* r, uint32_t addr) {
    asm volatile("ldmatrix.sync.aligned.m8n8.x4.trans.shared.b16 {%0,%1,%2,%3}, [%4];"
                 : "=r"(r[0]), "=r"(r[1]), "=r"(r[2]), "=r"(r[3]) : "r"(addr));
}

__device__ __forceinline__ void mma16816(float* c, const uint32_t* a, const uint32_t* b) {
    asm volatile("mma.sync.aligned.m16n8k16.row.col.f32.f16.f16.f32 "
                 "{%0,%1,%2,%3}, {%4,%5,%6,%7}, {%8,%9}, {%0,%1,%2,%3};"
                 : "+f"(c[0]), "+f"(c[1]), "+f"(c[2]), "+f"(c[3])
                 : "r"(a[0]), "r"(a[1]), "r"(a[2]), "r"(a[3]),
                   "r"(b[0]), "r"(b[1]));
}

// ---------------- conversion kernel (streaming f32 -> f16) ------------------
__global__ __launch_bounds__(256) void convert_f16(
    const float* __restrict__ src, f16* __restrict__ dst, int n4)
{
    int i = blockIdx.x * 256 + threadIdx.x;
    if (i >= n4) return;
    float4 v = ((const float4*)src)[i];
    __half2 a = __floats2half2_rn(v.x, v.y);
    __half2 b = __floats2half2_rn(v.z, v.w);
    ((uint2*)dst)[i] = make_uint2(*(uint32_t*)&a, *(uint32_t*)&b);
}

// ---------------- HMMA grouped GEMM ------------------------------------------
// CTA 128m x 128n, BK=64, 256 threads (8 warps, 2m x 4n, warp 64x32).
// A smem: [m][k] 128B rows, SW128.  B smem: [k][n] 256B rows, chunk^k swizzle.
constexpr int BM = 128, BK = 64;
constexpr int A_SZ = BM * BK * 2;                // 16384
constexpr int B_SZ = BK * 128 * 2;               // 16384
constexpr int STAGE_SZ = A_SZ + B_SZ;            // 32768
constexpr int NSTAGE = 3;
constexpr int SMEM_BYTES = NSTAGE * STAGE_SZ;    // 98304 -> 2 CTAs/SM

template <int K, bool FUSED>
__global__ __launch_bounds__(256, 2) void moe_gemm_hmma(
    const f16* __restrict__ A, const f16* __restrict__ B,
    float* __restrict__ Cout, f16* __restrict__ H,
    const void* __restrict__ tpe)
{
    const int e = blockIdx.z;
    int off, cnt;
    load_offsets(tpe, e, off, cnt);
    const int m0 = blockIdx.y * BM;
    if (m0 >= cnt) return;
    const int n0 = blockIdx.x * (FUSED ? 64 : 128);
    constexpr int NFULL = FUSED ? 2 * INTER : HIDDEN;

    extern __shared__ char smem[];
    const uint32_t sbase = smem_u32(smem);
    const int tid = threadIdx.x, wid = tid >> 5, lane = tid & 31;

    const f16* Ag = A + (size_t)off * K;
    const f16* Bg = B + (size_t)e * ((size_t)K * NFULL);

    // Warp tile: 64m x 32n; warps 2(m) x 4(n)
    const int wm = (wid & 1) * 64;
    const int wn = (wid >> 1) * 32;
    const int g = lane >> 3, r8 = lane & 7;

    int a_base[4];
#pragma unroll
    for (int mi = 0; mi < 4; mi++)
        a_base[mi] = (wm + mi * 16 + r8 + (g & 1) * 8) * 128 + (g >> 1) * 16;

    // B ldmatrix(.trans) lane setup: row k = (g&1)*8 + r8 within k16 step,
    // chunk index = ((wn>>3) + j*2 + (g>>1)) ^ r8.
    const int b_k_byte = ((g & 1) * 8 + r8) * 256;
    const int b_chunk_half = (g >> 1);

    // cooperative load indices
    const int a_row0 = tid >> 3, a_ks = tid & 7;   // A: 1024 16B units / 4 iters
    const int b_k0 = tid >> 4, b_c = tid & 15;     // B: 1024 16B units / 4 iters

    float acc[4][4][4];
#pragma unroll
    for (int mi = 0; mi < 4; mi++)
#pragma unroll
        for (int ni = 0; ni < 4; ni++)
#pragma unroll
            for (int q = 0; q < 4; q++) acc[mi][ni][q] = 0.0f;

    constexpr int NCH = K / BK;

    auto load_stage = [&](int c) {
        const uint32_t st = sbase + (c % NSTAGE) * STAGE_SZ;
        const int k0 = c * BK;
#pragma unroll
        for (int i = 0; i < 4; ++i) {
            int row = a_row0 + i * 32;
            int gr = m0 + row;
            int nb = (gr < cnt) ? 16 : 0;
            int grc = (gr < cnt) ? gr : 0;
            cp16(st + SW128(row * 128 + a_ks * 16),
                 Ag + (size_t)grc * K + k0 + a_ks * 8, nb);
        }
#pragma unroll
        for (int i = 0; i < 4; ++i) {
            int k = b_k0 + i * 16;
            int wc = b_c ^ (k & 7);
            int gcol = FUSED ? ((b_c < 8) ? (n0 + b_c * 8)
                                          : (INTER + n0 + (b_c - 8) * 8))
                             : (n0 + b_c * 8);
            cp16(st + A_SZ + k * 256 + wc * 16,
                 Bg + (size_t)(k0 + k) * NFULL + gcol, 16);
        }
        asm volatile("cp.async.commit_group;" ::: "memory");
    };

    load_stage(0);
    if (NCH > 1) load_stage(1);

    for (int c = 0; c < NCH; ++c) {
        // Round-5 proven order: issue prefetch FIRST, then bounded wait.
        if (c + 2 < NCH) {
            load_stage(c + 2);
            asm volatile("cp.async.wait_group 2;" ::: "memory");
        } else if (c + 1 < NCH) {
            asm volatile("cp.async.wait_group 1;" ::: "memory");
        } else {
            asm volatile("cp.async.wait_group 0;" ::: "memory");
        }
        __syncthreads();

        const uint32_t st = sbase + (c % NSTAGE) * STAGE_SZ;
        const uint32_t sA = st, sB = st + A_SZ;

#pragma unroll
        for (int kk = 0; kk < 4; ++kk) {
            // B fragments for this k16: 2 x4.trans -> 4 n8 frags (plain locals)
            uint32_t b[4][2];
#pragma unroll
            for (int j = 0; j < 2; ++j) {
                int chunk = (((wn >> 3) + j * 2 + b_chunk_half) ^ r8) & 15;
                uint32_t t[4];
                ldmx4t(t, sB + kk * 16 * 256 + b_k_byte + chunk * 16);
                b[j * 2][0] = t[0];     b[j * 2][1] = t[1];
                b[j * 2 + 1][0] = t[2]; b[j * 2 + 1][1] = t[3];
            }
#pragma unroll
            for (int mi = 0; mi < 4; mi++) {
                uint32_t a[4];
                ldmx4(a, sA + SW128(a_base[mi] + kk * 32));
#pragma unroll
                for (int ni = 0; ni < 4; ni++)
                    mma16816(acc[mi][ni], a, b[ni]);
            }
        }
        __syncthreads();
    }

    // ---------------- epilogue: stage accum through SMEM ----------------
    float* shf = (float*)smem;   // [128][132] fp32 = 67.6 KB (< 96 KB)
    const int crow = wm + (lane >> 2);
    const int ccol0 = wn + (lane & 3) * 2;
#pragma unroll
    for (int mi = 0; mi < 4; mi++)
#pragma unroll
        for (int ni = 0; ni < 4; ni++) {
            int rr = crow + mi * 16, cc = ccol0 + ni * 8;
            *(float2*)&shf[rr * 132 + cc]       = make_float2(acc[mi][ni][0], acc[mi][ni][1]);
            *(float2*)&shf[(rr + 8) * 132 + cc] = make_float2(acc[mi][ni][2], acc[mi][ni][3]);
        }
    __syncthreads();

    if (FUSED) {
        // cols [0,64) = gate(n0+j), [64,128) = up(n0+j); h = silu(g)*u
        for (int idx = tid; idx < 128 * 32; idx += 256) {
            int rr = idx >> 5, j = (idx & 31) * 2;
            if (m0 + rr >= cnt) continue;
            float g0 = shf[rr * 132 + j],      g1 = shf[rr * 132 + j + 1];
            float u0 = shf[rr * 132 + 64 + j], u1 = shf[rr * 132 + 64 + j + 1];
            float h0 = u0 * g0 / (1.0f + __expf(-g0));
            float h1 = u1 * g1 / (1.0f + __expf(-g1));
            __half2 hp = __floats2half2_rn(h0, h1);
            *(uint32_t*)(H + (size_t)(off + m0 + rr) * INTER + n0 + j) =
                *(uint32_t*)&hp;
        }
    } else {
        for (int idx = tid; idx < 128 * 32; idx += 256) {
            int rr = idx >> 5, cu = idx & 31;
            if (m0 + rr >= cnt) continue;
            *(float4*)(Cout + (size_t)(off + m0 + rr) * HIDDEN + n0 + cu * 4) =
                *(float4*)&shf[rr * 132 + cu * 4];
        }
    }
}

// ---------------- launch -----------------------------------------------------
extern "C" void kernel_launch(void* const* d_in, const int* in_sizes, int n_in,
                              void* d_out, int out_size) {
    const float* x    = (const float*)d_in[0];
    const float* w1   = (const float*)d_in[1];
    const float* w2   = (const float*)d_in[2];
    const void*  tpe  = d_in[3];
    float* out = (float*)d_out;

    f16 *xf, *w1f, *w2f, *hf;
    cudaGetSymbolAddress((void**)&xf,  g_x);
    cudaGetSymbolAddress((void**)&w1f, g_w1);
    cudaGetSymbolAddress((void**)&w2f, g_w2);
    cudaGetSymbolAddress((void**)&hf,  g_h);

    int nx = TOKENS * HIDDEN / 4;
    int n1 = NEXP * HIDDEN * 2 * INTER / 4;
    int n2 = NEXP * INTER * HIDDEN / 4;
    convert_f16<<<(nx + 255) / 256, 256>>>(x, xf, nx);
    convert_f16<<<(n1 + 255) / 256, 256>>>(w1, w1f, n1);
    convert_f16<<<(n2 + 255) / 256, 256>>>(w2, w2f, n2);

    cudaFuncSetAttribute(moe_gemm_hmma<HIDDEN, true>,
                         cudaFuncAttributeMaxDynamicSharedMemorySize, SMEM_BYTES);
    cudaFuncSetAttribute(moe_gemm_hmma<INTER, false>,
                         cudaFuncAttributeMaxDynamicSharedMemorySize, SMEM_BYTES);

    // GEMM1 (fused swiglu): each n-tile covers 64 gate + 64 up columns
    moe_gemm_hmma<HIDDEN, true><<<dim3(INTER / 64, TOKENS / 128, NEXP), 256, SMEM_BYTES>>>(
        xf, w1f, nullptr, hf, tpe);
    // GEMM2
    moe_gemm_hmma<INTER, false><<<dim3(HIDDEN / 128, TOKENS / 128, NEXP), 256, SMEM_BYTES>>>(
        hf, w2f, out, nullptr, tpe);
}